// round 1
// baseline (speedup 1.0000x reference)
#include <cuda_runtime.h>

// Problem constants
constexpr int NB = 8;     // batch
constexpr int NC = 512;   // channels
constexpr int NW = 2048;  // width (sequence)
constexpr int NQ = 64;    // C/8 (qk head dim)

// Scratch (device globals; allocation-free per harness rules)
__device__ float g_q[NB * NQ * NW];             // [b, q, i]
__device__ float g_k[NB * NQ * NW];             // [b, q, j]
__device__ float g_v[NB * NC * NW];             // [b, c, j]
__device__ float g_att[(size_t)NB * NW * NW];   // energy -> attn, [b, i, j]

// ---------------- packed fp32x2 helpers (sm_103a full-rate fp32 path) -------

__device__ __forceinline__ unsigned long long pk(float lo, float hi) {
    unsigned long long r;
    asm("mov.b64 %0, {%1, %2};" : "=l"(r) : "f"(lo), "f"(hi));
    return r;
}

__device__ __forceinline__ float2 upk(unsigned long long v) {
    float2 r;
    asm("mov.b64 {%0, %1}, %2;" : "=f"(r.x), "=f"(r.y) : "l"(v));
    return r;
}

// One k-step of the 8x8 microtile: acc[i][jp] += a[i] * (b[2jp], b[2jp+1])
__device__ __forceinline__ void micro_fma(unsigned long long acc[8][4],
                                          const float* __restrict__ rowA,
                                          const float* __restrict__ rowB) {
    float a[8], bb[8];
    *(float4*)&a[0]  = *(const float4*)(rowA);
    *(float4*)&a[4]  = *(const float4*)(rowA + 4);
    *(float4*)&bb[0] = *(const float4*)(rowB);
    *(float4*)&bb[4] = *(const float4*)(rowB + 4);
    unsigned long long bp[4];
    bp[0] = pk(bb[0], bb[1]);
    bp[1] = pk(bb[2], bb[3]);
    bp[2] = pk(bb[4], bb[5]);
    bp[3] = pk(bb[6], bb[7]);
#pragma unroll
    for (int i = 0; i < 8; i++) {
        unsigned long long ap = pk(a[i], a[i]);
#pragma unroll
        for (int j = 0; j < 4; j++)
            asm("fma.rn.f32x2 %0, %1, %2, %0;"
                : "+l"(acc[i][j]) : "l"(ap), "l"(bp[j]));
    }
}

__device__ __forceinline__ void acc_zero(unsigned long long acc[8][4]) {
#pragma unroll
    for (int i = 0; i < 8; i++)
#pragma unroll
        for (int j = 0; j < 4; j++) acc[i][j] = 0ull;
}

// ---------------- Kernel 1: fused QKV (1x1 conv == channel GEMM) ------------
// Y[m, w] = sum_c Wall[m, c] * x[b, c, w] + bias[m],  m in [0, 640)
// m<64 -> q channel m ; m<128 -> k channel m-64 ; else v channel m-128.
// Outputs stored [b, ch, w] so later GEMMs are K-major on both operands.

__global__ void __launch_bounds__(256, 2)
qkv_kernel(const float* __restrict__ x,
           const float* __restrict__ Wq, const float* __restrict__ bq,
           const float* __restrict__ Wk, const float* __restrict__ bk,
           const float* __restrict__ Wv, const float* __restrict__ bv) {
    __shared__ float sW[16][128];  // [k][m]  (transposed on store)
    __shared__ float sX[16][128];  // [k][w]  (direct)
    const int b  = blockIdx.z;
    const int m0 = blockIdx.y * 128;
    const int w0 = blockIdx.x * 128;
    const int tid = threadIdx.x;
    const int ty = tid >> 4, tx = tid & 15;

    unsigned long long acc[8][4];
    acc_zero(acc);

    for (int kk = 0; kk < NC; kk += 16) {
#pragma unroll
        for (int p = 0; p < 2; p++) {
            int idx = tid + p * 256;
            // weight tile: 128 rows x 16 cols, float4 per (row, quarter)
            int r  = idx >> 2;
            int c4 = (idx & 3) << 2;
            int m  = m0 + r;
            const float* src;
            if (m < NQ)            src = Wq + (size_t)m * NC;
            else if (m < 2 * NQ)   src = Wk + (size_t)(m - NQ) * NC;
            else                   src = Wv + (size_t)(m - 2 * NQ) * NC;
            float4 w4 = *(const float4*)(src + kk + c4);
            sW[c4 + 0][r] = w4.x; sW[c4 + 1][r] = w4.y;
            sW[c4 + 2][r] = w4.z; sW[c4 + 3][r] = w4.w;
            // x tile: 16 rows x 128 cols, direct coalesced
            int r2  = idx >> 5;
            int c42 = (idx & 31) << 2;
            *(float4*)&sX[r2][c42] =
                *(const float4*)(x + ((size_t)b * NC + kk + r2) * NW + w0 + c42);
        }
        __syncthreads();
#pragma unroll
        for (int k = 0; k < 16; k++)
            micro_fma(acc, &sW[k][ty * 8], &sX[k][tx * 8]);
        __syncthreads();
    }

#pragma unroll
    for (int i = 0; i < 8; i++) {
        int m = m0 + ty * 8 + i;
        float bias;
        float* dst;
        if (m < NQ)          { bias = bq[m];          dst = g_q + ((size_t)b * NQ + m) * NW; }
        else if (m < 2 * NQ) { bias = bk[m - NQ];     dst = g_k + ((size_t)b * NQ + (m - NQ)) * NW; }
        else                 { bias = bv[m - 2 * NQ]; dst = g_v + ((size_t)b * NC + (m - 2 * NQ)) * NW; }
        float o[8];
#pragma unroll
        for (int j = 0; j < 4; j++) {
            float2 t = upk(acc[i][j]);
            o[2 * j] = t.x + bias; o[2 * j + 1] = t.y + bias;
        }
        *(float4*)(dst + w0 + tx * 8)     = make_float4(o[0], o[1], o[2], o[3]);
        *(float4*)(dst + w0 + tx * 8 + 4) = make_float4(o[4], o[5], o[6], o[7]);
    }
}

// ---------------- Kernel 2: energy E[b,i,j] = sum_q q[b,q,i]*k[b,q,j] -------
// Both operands are [b, q, pos]: K-major in gmem -> direct smem fills.

__global__ void __launch_bounds__(256, 2)
energy_kernel() {
    __shared__ float sQ[16][128];  // [q][i]
    __shared__ float sK[16][128];  // [q][j]
    const int b  = blockIdx.z;
    const int i0 = blockIdx.y * 128;
    const int j0 = blockIdx.x * 128;
    const int tid = threadIdx.x;
    const int ty = tid >> 4, tx = tid & 15;

    unsigned long long acc[8][4];
    acc_zero(acc);

    for (int kk = 0; kk < NQ; kk += 16) {
#pragma unroll
        for (int p = 0; p < 2; p++) {
            int idx = tid + p * 256;
            int r  = idx >> 5;
            int c4 = (idx & 31) << 2;
            *(float4*)&sQ[r][c4] =
                *(const float4*)(g_q + ((size_t)b * NQ + kk + r) * NW + i0 + c4);
            *(float4*)&sK[r][c4] =
                *(const float4*)(g_k + ((size_t)b * NQ + kk + r) * NW + j0 + c4);
        }
        __syncthreads();
#pragma unroll
        for (int k = 0; k < 16; k++)
            micro_fma(acc, &sQ[k][ty * 8], &sK[k][tx * 8]);
        __syncthreads();
    }

#pragma unroll
    for (int i = 0; i < 8; i++) {
        float* dst = g_att + ((size_t)b * NW + i0 + ty * 8 + i) * NW + j0 + tx * 8;
        float o[8];
#pragma unroll
        for (int j = 0; j < 4; j++) {
            float2 t = upk(acc[i][j]);
            o[2 * j] = t.x; o[2 * j + 1] = t.y;
        }
        *(float4*)(dst)     = make_float4(o[0], o[1], o[2], o[3]);
        *(float4*)(dst + 4) = make_float4(o[4], o[5], o[6], o[7]);
    }
}

// ---------------- Kernel 3: row softmax over g_att, in place ----------------

__global__ void __launch_bounds__(256)
softmax_kernel() {
    __shared__ float red[8];
    const int row = blockIdx.x;           // b*NW + i
    float* p = g_att + (size_t)row * NW;
    const int tid = threadIdx.x;

    float4 v0 = *(float4*)(p + tid * 8);
    float4 v1 = *(float4*)(p + tid * 8 + 4);
    float e[8] = {v0.x, v0.y, v0.z, v0.w, v1.x, v1.y, v1.z, v1.w};

    float m = e[0];
#pragma unroll
    for (int i = 1; i < 8; i++) m = fmaxf(m, e[i]);
#pragma unroll
    for (int o = 16; o; o >>= 1) m = fmaxf(m, __shfl_xor_sync(0xffffffffu, m, o));
    if ((tid & 31) == 0) red[tid >> 5] = m;
    __syncthreads();
    m = red[0];
#pragma unroll
    for (int i = 1; i < 8; i++) m = fmaxf(m, red[i]);

    float s = 0.f;
#pragma unroll
    for (int i = 0; i < 8; i++) { e[i] = __expf(e[i] - m); s += e[i]; }
#pragma unroll
    for (int o = 16; o; o >>= 1) s += __shfl_xor_sync(0xffffffffu, s, o);
    __syncthreads();  // red reuse
    if ((tid & 31) == 0) red[tid >> 5] = s;
    __syncthreads();
    s = 0.f;
#pragma unroll
    for (int i = 0; i < 8; i++) s += red[i];

    float inv = 1.0f / s;
#pragma unroll
    for (int i = 0; i < 8; i++) e[i] *= inv;
    *(float4*)(p + tid * 8)     = make_float4(e[0], e[1], e[2], e[3]);
    *(float4*)(p + tid * 8 + 4) = make_float4(e[4], e[5], e[6], e[7]);
}

// ---------------- Kernel 4: out[b,c,i] = gamma*sum_j v[b,c,j]*attn[b,i,j] + x

__global__ void __launch_bounds__(256, 2)
out_kernel(const float* __restrict__ x, const float* __restrict__ gamma,
           float* __restrict__ out) {
    __shared__ float sV[16][128];  // [j][c] (transposed on store)
    __shared__ float sA[16][128];  // [j][i] (transposed on store)
    const int b  = blockIdx.z;
    const int c0 = blockIdx.y * 128;
    const int i0 = blockIdx.x * 128;
    const int tid = threadIdx.x;
    const int ty = tid >> 4, tx = tid & 15;

    unsigned long long acc[8][4];
    acc_zero(acc);

    for (int kk = 0; kk < NW; kk += 16) {
#pragma unroll
        for (int p = 0; p < 2; p++) {
            int idx = tid + p * 256;
            int r  = idx >> 2;
            int c4 = (idx & 3) << 2;
            float4 vv = *(const float4*)(g_v + ((size_t)b * NC + c0 + r) * NW + kk + c4);
            sV[c4 + 0][r] = vv.x; sV[c4 + 1][r] = vv.y;
            sV[c4 + 2][r] = vv.z; sV[c4 + 3][r] = vv.w;
            float4 av = *(const float4*)(g_att + ((size_t)b * NW + i0 + r) * NW + kk + c4);
            sA[c4 + 0][r] = av.x; sA[c4 + 1][r] = av.y;
            sA[c4 + 2][r] = av.z; sA[c4 + 3][r] = av.w;
        }
        __syncthreads();
#pragma unroll
        for (int k = 0; k < 16; k++)
            micro_fma(acc, &sV[k][ty * 8], &sA[k][tx * 8]);
        __syncthreads();
    }

    const float g = gamma[0];
#pragma unroll
    for (int i = 0; i < 8; i++) {
        int c = c0 + ty * 8 + i;
        size_t base = ((size_t)b * NC + c) * NW + i0 + tx * 8;
        float o[8];
#pragma unroll
        for (int j = 0; j < 4; j++) {
            float2 t = upk(acc[i][j]);
            o[2 * j] = t.x; o[2 * j + 1] = t.y;
        }
        float4 x0 = *(const float4*)(x + base);
        float4 x1 = *(const float4*)(x + base + 4);
        *(float4*)(out + base) =
            make_float4(fmaf(g, o[0], x0.x), fmaf(g, o[1], x0.y),
                        fmaf(g, o[2], x0.z), fmaf(g, o[3], x0.w));
        *(float4*)(out + base + 4) =
            make_float4(fmaf(g, o[4], x1.x), fmaf(g, o[5], x1.y),
                        fmaf(g, o[6], x1.z), fmaf(g, o[7], x1.w));
    }
}

// ---------------- launch ----------------------------------------------------

extern "C" void kernel_launch(void* const* d_in, const int* in_sizes, int n_in,
                              void* d_out, int out_size) {
    const float* x     = (const float*)d_in[0];
    const float* Wq    = (const float*)d_in[1];
    const float* bq    = (const float*)d_in[2];
    const float* Wk    = (const float*)d_in[3];
    const float* bk    = (const float*)d_in[4];
    const float* Wv    = (const float*)d_in[5];
    const float* bv    = (const float*)d_in[6];
    const float* gamma = (const float*)d_in[7];
    float* out = (float*)d_out;

    qkv_kernel<<<dim3(NW / 128, (NC + 2 * NQ) / 128, NB), 256>>>(
        x, Wq, bq, Wk, bk, Wv, bv);
    energy_kernel<<<dim3(NW / 128, NW / 128, NB), 256>>>();
    softmax_kernel<<<NB * NW, 256>>>();
    out_kernel<<<dim3(NW / 128, NC / 128, NB), 256>>>(x, gamma, out);
}

// round 3
// speedup vs baseline: 1.6238x; 1.6238x over previous
#include <cuda_runtime.h>
#include <cuda_bf16.h>
#include <cstdint>

// Problem constants
constexpr int NB = 8;     // batch
constexpr int NC = 512;   // channels
constexpr int NW = 2048;  // width (sequence)
constexpr int NQ = 64;    // C/8 (qk head dim)

// Scratch (device globals; allocation-free per harness rules)
__device__ float g_q[NB * NQ * NW];             // [b, q, i]
__device__ float g_k[NB * NQ * NW];             // [b, q, j]
__device__ float g_v[NB * NC * NW];             // [b, c, j]
__device__ float g_att[(size_t)NB * NW * NW];   // energy -> attn, [b, i, j]

// ---------------- packed fp32x2 helpers (SIMT kernels) ----------------------

__device__ __forceinline__ unsigned long long pk(float lo, float hi) {
    unsigned long long r;
    asm("mov.b64 %0, {%1, %2};" : "=l"(r) : "f"(lo), "f"(hi));
    return r;
}

__device__ __forceinline__ float2 upk(unsigned long long v) {
    float2 r;
    asm("mov.b64 {%0, %1}, %2;" : "=f"(r.x), "=f"(r.y) : "l"(v));
    return r;
}

__device__ __forceinline__ void micro_fma(unsigned long long acc[8][4],
                                          const float* __restrict__ rowA,
                                          const float* __restrict__ rowB) {
    float a[8], bb[8];
    *(float4*)&a[0]  = *(const float4*)(rowA);
    *(float4*)&a[4]  = *(const float4*)(rowA + 4);
    *(float4*)&bb[0] = *(const float4*)(rowB);
    *(float4*)&bb[4] = *(const float4*)(rowB + 4);
    unsigned long long bp[4];
    bp[0] = pk(bb[0], bb[1]);
    bp[1] = pk(bb[2], bb[3]);
    bp[2] = pk(bb[4], bb[5]);
    bp[3] = pk(bb[6], bb[7]);
#pragma unroll
    for (int i = 0; i < 8; i++) {
        unsigned long long ap = pk(a[i], a[i]);
#pragma unroll
        for (int j = 0; j < 4; j++)
            asm("fma.rn.f32x2 %0, %1, %2, %0;"
                : "+l"(acc[i][j]) : "l"(ap), "l"(bp[j]));
    }
}

__device__ __forceinline__ void acc_zero(unsigned long long acc[8][4]) {
#pragma unroll
    for (int i = 0; i < 8; i++)
#pragma unroll
        for (int j = 0; j < 4; j++) acc[i][j] = 0ull;
}

// ---------------- mma.sync helpers (sm_80-class, works on plain sm_103) -----

__device__ __forceinline__ uint32_t smem_u32(const void* p) {
    uint32_t a;
    asm("{ .reg .u64 t; cvta.to.shared.u64 t, %1; cvt.u32.u64 %0, t; }"
        : "=r"(a) : "l"(p));
    return a;
}

#define LDSM_X4(R0, R1, R2, R3, A)                                            \
    asm volatile("ldmatrix.sync.aligned.m8n8.x4.shared.b16 {%0,%1,%2,%3}, [%4];" \
                 : "=r"(R0), "=r"(R1), "=r"(R2), "=r"(R3) : "r"(A))

#define MMA_BF16(c, a, b)                                                     \
    asm volatile("mma.sync.aligned.m16n8k16.row.col.f32.bf16.bf16.f32 "       \
                 "{%0,%1,%2,%3}, {%4,%5,%6,%7}, {%8,%9}, {%0,%1,%2,%3};"      \
                 : "+f"((c)[0]), "+f"((c)[1]), "+f"((c)[2]), "+f"((c)[3])     \
                 : "r"((a)[0]), "r"((a)[1]), "r"((a)[2]), "r"((a)[3]),        \
                   "r"((b)[0]), "r"((b)[1]))

// ---------------- Kernel 1: fused QKV (1x1 conv == channel GEMM) ------------

__global__ void __launch_bounds__(256, 2)
qkv_kernel(const float* __restrict__ x,
           const float* __restrict__ Wq, const float* __restrict__ bq,
           const float* __restrict__ Wk, const float* __restrict__ bk,
           const float* __restrict__ Wv, const float* __restrict__ bv) {
    __shared__ float sW[16][128];
    __shared__ float sX[16][128];
    const int b  = blockIdx.z;
    const int m0 = blockIdx.y * 128;
    const int w0 = blockIdx.x * 128;
    const int tid = threadIdx.x;
    const int ty = tid >> 4, tx = tid & 15;

    unsigned long long acc[8][4];
    acc_zero(acc);

    for (int kk = 0; kk < NC; kk += 16) {
#pragma unroll
        for (int p = 0; p < 2; p++) {
            int idx = tid + p * 256;
            int r  = idx >> 2;
            int c4 = (idx & 3) << 2;
            int m  = m0 + r;
            const float* src;
            if (m < NQ)            src = Wq + (size_t)m * NC;
            else if (m < 2 * NQ)   src = Wk + (size_t)(m - NQ) * NC;
            else                   src = Wv + (size_t)(m - 2 * NQ) * NC;
            float4 w4 = *(const float4*)(src + kk + c4);
            sW[c4 + 0][r] = w4.x; sW[c4 + 1][r] = w4.y;
            sW[c4 + 2][r] = w4.z; sW[c4 + 3][r] = w4.w;
            int r2  = idx >> 5;
            int c42 = (idx & 31) << 2;
            *(float4*)&sX[r2][c42] =
                *(const float4*)(x + ((size_t)b * NC + kk + r2) * NW + w0 + c42);
        }
        __syncthreads();
#pragma unroll
        for (int k = 0; k < 16; k++)
            micro_fma(acc, &sW[k][ty * 8], &sX[k][tx * 8]);
        __syncthreads();
    }

#pragma unroll
    for (int i = 0; i < 8; i++) {
        int m = m0 + ty * 8 + i;
        float bias;
        float* dst;
        if (m < NQ)          { bias = bq[m];          dst = g_q + ((size_t)b * NQ + m) * NW; }
        else if (m < 2 * NQ) { bias = bk[m - NQ];     dst = g_k + ((size_t)b * NQ + (m - NQ)) * NW; }
        else                 { bias = bv[m - 2 * NQ]; dst = g_v + ((size_t)b * NC + (m - 2 * NQ)) * NW; }
        float o[8];
#pragma unroll
        for (int j = 0; j < 4; j++) {
            float2 t = upk(acc[i][j]);
            o[2 * j] = t.x + bias; o[2 * j + 1] = t.y + bias;
        }
        *(float4*)(dst + w0 + tx * 8)     = make_float4(o[0], o[1], o[2], o[3]);
        *(float4*)(dst + w0 + tx * 8 + 4) = make_float4(o[4], o[5], o[6], o[7]);
    }
}

// ---------------- Kernel 2: energy E[b,i,j] = sum_q q[b,q,i]*k[b,q,j] -------

__global__ void __launch_bounds__(256, 2)
energy_kernel() {
    __shared__ float sQ[16][128];
    __shared__ float sK[16][128];
    const int b  = blockIdx.z;
    const int i0 = blockIdx.y * 128;
    const int j0 = blockIdx.x * 128;
    const int tid = threadIdx.x;
    const int ty = tid >> 4, tx = tid & 15;

    unsigned long long acc[8][4];
    acc_zero(acc);

    for (int kk = 0; kk < NQ; kk += 16) {
#pragma unroll
        for (int p = 0; p < 2; p++) {
            int idx = tid + p * 256;
            int r  = idx >> 5;
            int c4 = (idx & 31) << 2;
            *(float4*)&sQ[r][c4] =
                *(const float4*)(g_q + ((size_t)b * NQ + kk + r) * NW + i0 + c4);
            *(float4*)&sK[r][c4] =
                *(const float4*)(g_k + ((size_t)b * NQ + kk + r) * NW + j0 + c4);
        }
        __syncthreads();
#pragma unroll
        for (int k = 0; k < 16; k++)
            micro_fma(acc, &sQ[k][ty * 8], &sK[k][tx * 8]);
        __syncthreads();
    }

#pragma unroll
    for (int i = 0; i < 8; i++) {
        float* dst = g_att + ((size_t)b * NW + i0 + ty * 8 + i) * NW + j0 + tx * 8;
        float o[8];
#pragma unroll
        for (int j = 0; j < 4; j++) {
            float2 t = upk(acc[i][j]);
            o[2 * j] = t.x; o[2 * j + 1] = t.y;
        }
        *(float4*)(dst)     = make_float4(o[0], o[1], o[2], o[3]);
        *(float4*)(dst + 4) = make_float4(o[4], o[5], o[6], o[7]);
    }
}

// ---------------- Kernel 3: row softmax over g_att, in place ----------------

__global__ void __launch_bounds__(256)
softmax_kernel() {
    __shared__ float red[8];
    const int row = blockIdx.x;
    float* p = g_att + (size_t)row * NW;
    const int tid = threadIdx.x;

    float4 v0 = *(float4*)(p + tid * 8);
    float4 v1 = *(float4*)(p + tid * 8 + 4);
    float e[8] = {v0.x, v0.y, v0.z, v0.w, v1.x, v1.y, v1.z, v1.w};

    float m = e[0];
#pragma unroll
    for (int i = 1; i < 8; i++) m = fmaxf(m, e[i]);
#pragma unroll
    for (int o = 16; o; o >>= 1) m = fmaxf(m, __shfl_xor_sync(0xffffffffu, m, o));
    if ((tid & 31) == 0) red[tid >> 5] = m;
    __syncthreads();
    m = red[0];
#pragma unroll
    for (int i = 1; i < 8; i++) m = fmaxf(m, red[i]);

    float s = 0.f;
#pragma unroll
    for (int i = 0; i < 8; i++) { e[i] = __expf(e[i] - m); s += e[i]; }
#pragma unroll
    for (int o = 16; o; o >>= 1) s += __shfl_xor_sync(0xffffffffu, s, o);
    __syncthreads();
    if ((tid & 31) == 0) red[tid >> 5] = s;
    __syncthreads();
    s = 0.f;
#pragma unroll
    for (int i = 0; i < 8; i++) s += red[i];

    float inv = 1.0f / s;
#pragma unroll
    for (int i = 0; i < 8; i++) e[i] *= inv;
    *(float4*)(p + tid * 8)     = make_float4(e[0], e[1], e[2], e[3]);
    *(float4*)(p + tid * 8 + 4) = make_float4(e[4], e[5], e[6], e[7]);
}

// ---------------- Kernel 4 (mma.sync bf16 split-2): --------------------------
// out[b, c, i] = gamma * sum_j v[b,c,j] * att[b,i,j] + x[b,c,i]
// A = v[c, j] (row-major M x K), B = att[i, j] ("col-major" K x N, n-major).
// Each fp32 operand splits exactly: hi = top 16 bits (bf16 truncation, exact),
// lo = bf16(x - hi).  acc += Ah*Bh + Ah*Bl + Al*Bh in fp32.

constexpr int CH   = 32;                   // K elements per chunk
constexpr int SROW = 72;                   // smem row stride in bf16 (144 B, padded)
constexpr int TILE_HB = 128 * SROW * 2;    // bytes per (hi+lo) tile = 18432
constexpr int OUT_SMEM = 4 * TILE_HB;      // A0,B0,A1,B1 = 73728 B

__global__ void __launch_bounds__(256, 1)
out_mma_kernel(const float* __restrict__ x, const float* __restrict__ gamma,
               float* __restrict__ out) {
    extern __shared__ uint16_t smem[];     // [4][128][72] bf16

    const int b  = blockIdx.z;
    const int c0 = blockIdx.x * 128;       // x fastest: c-blocks share att tile in L2
    const int i0 = blockIdx.y * 128;
    const int tid  = threadIdx.x;
    const int wid  = tid >> 5;
    const int lane = tid & 31;
    const int wm = wid >> 2;               // 0..1  (M = 64 per warp)
    const int wn = wid & 3;                // 0..3  (N = 32 per warp)

    const uint32_t sbase = smem_u32(smem);

    // loader mapping: 2 threads per row, each covers 16 columns
    const int lrow = tid >> 1;
    const int lcol = (tid & 1) * 16;
    const float* gA = g_v   + ((size_t)b * NC + c0 + lrow) * NW + lcol;
    const float* gB = g_att + ((size_t)b * NW + i0 + lrow) * NW + lcol;

    float acc[4][4][4];
#pragma unroll
    for (int mf = 0; mf < 4; mf++)
#pragma unroll
        for (int nf = 0; nf < 4; nf++)
#pragma unroll
            for (int e = 0; e < 4; e++) acc[mf][nf][e] = 0.f;

    float4 pa[4], pb[4];
#pragma unroll
    for (int q = 0; q < 4; q++) {
        pa[q] = *(const float4*)(gA + 4 * q);
        pb[q] = *(const float4*)(gB + 4 * q);
    }

#pragma unroll 1
    for (int chunk = 0; chunk < NW / CH; chunk++) {
        const int p = chunk & 1;
        uint16_t* sA = smem + p * (2 * TILE_HB / 2);
        uint16_t* sB = sA + TILE_HB / 2;

        // convert + store prefetched chunk into smem buffer p
#pragma unroll
        for (int q = 0; q < 4; q++) {
            const float* fa = (const float*)&pa[q];
            const float* fb = (const float*)&pb[q];
            uint32_t ah01, ah23, bh01, bh23;
            {
                uint32_t u0 = __float_as_uint(fa[0]), u1 = __float_as_uint(fa[1]);
                uint32_t u2 = __float_as_uint(fa[2]), u3 = __float_as_uint(fa[3]);
                ah01 = __byte_perm(u0, u1, 0x7632);
                ah23 = __byte_perm(u2, u3, 0x7632);
                float r0 = fa[0] - __uint_as_float(u0 & 0xFFFF0000u);
                float r1 = fa[1] - __uint_as_float(u1 & 0xFFFF0000u);
                float r2 = fa[2] - __uint_as_float(u2 & 0xFFFF0000u);
                float r3 = fa[3] - __uint_as_float(u3 & 0xFFFF0000u);
                __nv_bfloat162 l01 = __floats2bfloat162_rn(r0, r1);
                __nv_bfloat162 l23 = __floats2bfloat162_rn(r2, r3);
                uint2 hv = make_uint2(ah01, ah23);
                uint2 lv = make_uint2(*(uint32_t*)&l01, *(uint32_t*)&l23);
                *(uint2*)(sA + lrow * SROW + lcol + 4 * q)      = hv;
                *(uint2*)(sA + lrow * SROW + 32 + lcol + 4 * q) = lv;
            }
            {
                uint32_t u0 = __float_as_uint(fb[0]), u1 = __float_as_uint(fb[1]);
                uint32_t u2 = __float_as_uint(fb[2]), u3 = __float_as_uint(fb[3]);
                bh01 = __byte_perm(u0, u1, 0x7632);
                bh23 = __byte_perm(u2, u3, 0x7632);
                float r0 = fb[0] - __uint_as_float(u0 & 0xFFFF0000u);
                float r1 = fb[1] - __uint_as_float(u1 & 0xFFFF0000u);
                float r2 = fb[2] - __uint_as_float(u2 & 0xFFFF0000u);
                float r3 = fb[3] - __uint_as_float(u3 & 0xFFFF0000u);
                __nv_bfloat162 l01 = __floats2bfloat162_rn(r0, r1);
                __nv_bfloat162 l23 = __floats2bfloat162_rn(r2, r3);
                uint2 hv = make_uint2(bh01, bh23);
                uint2 lv = make_uint2(*(uint32_t*)&l01, *(uint32_t*)&l23);
                *(uint2*)(sB + lrow * SROW + lcol + 4 * q)      = hv;
                *(uint2*)(sB + lrow * SROW + 32 + lcol + 4 * q) = lv;
            }
        }
        __syncthreads();

        // prefetch next chunk
        if (chunk < NW / CH - 1) {
            const int kk = (chunk + 1) * CH;
#pragma unroll
            for (int q = 0; q < 4; q++) {
                pa[q] = *(const float4*)(gA + kk + 4 * q);
                pb[q] = *(const float4*)(gB + kk + 4 * q);
            }
        }

        // compute 2 k-steps of 16 from buffer p
        const uint32_t aBase = sbase + p * 2 * TILE_HB;
        const uint32_t bBase = aBase + TILE_HB;
#pragma unroll
        for (int ks = 0; ks < 2; ks++) {
            const int kb = ks * 16;
            uint32_t Ah[4][4], Al[4][4], Bh[4][2], Bl[4][2];
            // A fragments: m = wm*64 + mf*16 + (lane&15), k = kb + ((lane>>4)<<3)
            const int am = wm * 64 + (lane & 15);
            const int ak = kb + ((lane >> 4) << 3);
#pragma unroll
            for (int mf = 0; mf < 4; mf++) {
                uint32_t addr = aBase + ((am + mf * 16) * SROW + ak) * 2;
                LDSM_X4(Ah[mf][0], Ah[mf][1], Ah[mf][2], Ah[mf][3], addr);
                LDSM_X4(Al[mf][0], Al[mf][1], Al[mf][2], Al[mf][3], addr + 64);
            }
            // B fragments: n = wn*32 + nfp*16 + ((lane>>4)<<3) + (lane&7)
            //              k = kb + (((lane>>3)&1)<<3)
            const int bn = wn * 32 + ((lane >> 4) << 3) + (lane & 7);
            const int bk = kb + (((lane >> 3) & 1) << 3);
#pragma unroll
            for (int nfp = 0; nfp < 2; nfp++) {
                uint32_t addr = bBase + ((bn + nfp * 16) * SROW + bk) * 2;
                LDSM_X4(Bh[2 * nfp][0], Bh[2 * nfp][1],
                        Bh[2 * nfp + 1][0], Bh[2 * nfp + 1][1], addr);
                LDSM_X4(Bl[2 * nfp][0], Bl[2 * nfp][1],
                        Bl[2 * nfp + 1][0], Bl[2 * nfp + 1][1], addr + 64);
            }
#pragma unroll
            for (int mf = 0; mf < 4; mf++)
#pragma unroll
                for (int nf = 0; nf < 4; nf++) {
                    MMA_BF16(acc[mf][nf], Ah[mf], Bh[nf]);
                    MMA_BF16(acc[mf][nf], Ah[mf], Bl[nf]);
                    MMA_BF16(acc[mf][nf], Al[mf], Bh[nf]);
                }
        }
    }

    // epilogue: gamma * acc + x, direct to gmem
    const float gam = gamma[0];
#pragma unroll
    for (int mf = 0; mf < 4; mf++) {
        const int m = c0 + wm * 64 + mf * 16 + (lane >> 2);
#pragma unroll
        for (int nf = 0; nf < 4; nf++) {
            const int n = i0 + wn * 32 + nf * 8 + ((lane & 3) << 1);
            size_t o0 = ((size_t)b * NC + m) * NW + n;
            float2 xv0 = *(const float2*)(x + o0);
            float2 r0;
            r0.x = fmaf(gam, acc[mf][nf][0], xv0.x);
            r0.y = fmaf(gam, acc[mf][nf][1], xv0.y);
            *(float2*)(out + o0) = r0;
            size_t o1 = o0 + (size_t)8 * NW;
            float2 xv1 = *(const float2*)(x + o1);
            float2 r1;
            r1.x = fmaf(gam, acc[mf][nf][2], xv1.x);
            r1.y = fmaf(gam, acc[mf][nf][3], xv1.y);
            *(float2*)(out + o1) = r1;
        }
    }
}

// ---------------- launch ----------------------------------------------------

extern "C" void kernel_launch(void* const* d_in, const int* in_sizes, int n_in,
                              void* d_out, int out_size) {
    const float* x     = (const float*)d_in[0];
    const float* Wq    = (const float*)d_in[1];
    const float* bq    = (const float*)d_in[2];
    const float* Wk    = (const float*)d_in[3];
    const float* bk    = (const float*)d_in[4];
    const float* Wv    = (const float*)d_in[5];
    const float* bv    = (const float*)d_in[6];
    const float* gamma = (const float*)d_in[7];
    float* out = (float*)d_out;

    cudaFuncSetAttribute(out_mma_kernel,
                         cudaFuncAttributeMaxDynamicSharedMemorySize, OUT_SMEM);

    qkv_kernel<<<dim3(NW / 128, (NC + 2 * NQ) / 128, NB), 256>>>(
        x, Wq, bq, Wk, bk, Wv, bv);
    energy_kernel<<<dim3(NW / 128, NW / 128, NB), 256>>>();
    softmax_kernel<<<NB * NW, 256>>>();
    out_mma_kernel<<<dim3(NC / 128, NW / 128, NB), 256, OUT_SMEM>>>(x, gamma, out);
}

// round 6
// speedup vs baseline: 2.1809x; 1.3431x over previous
#include <cuda_runtime.h>
#include <cuda_bf16.h>
#include <cstdint>

// Problem constants
constexpr int NB = 8;     // batch
constexpr int NC = 512;   // channels
constexpr int NW = 2048;  // width (sequence)
constexpr int NQ = 64;    // C/8 (qk head dim)

// Scratch (device globals; allocation-free per harness rules).
// __align__(16): accessed as uint4.
__device__ __align__(16) uint16_t g_xth[(size_t)NB * NW * NC];   // x^T hi [b][w][c]
__device__ __align__(16) uint16_t g_xtl[(size_t)NB * NW * NC];   // x^T lo
__device__ __align__(16) uint16_t g_qkh[(size_t)NB * NW * 128];  // q|k hi [b][pos][ch]
__device__ __align__(16) uint16_t g_qkl[(size_t)NB * NW * 128];
__device__ __align__(16) uint16_t g_vh[(size_t)NB * NC * NW];    // v hi [b][c][j]
__device__ __align__(16) uint16_t g_vl[(size_t)NB * NC * NW];
__device__ __align__(16) float    g_att[(size_t)NB * NW * NW];   // energy S [b][i][j]
__device__ __align__(16) uint16_t g_ph[(size_t)NB * NW * NW];    // P hi [b][i][j]
__device__ __align__(16) uint16_t g_pl[(size_t)NB * NW * NW];

// ---------------- helpers ----------------------------------------------------

__device__ __forceinline__ uint32_t smem_u32(const void* p) {
    uint32_t a;
    asm("{ .reg .u64 t; cvta.to.shared.u64 t, %1; cvt.u32.u64 %0, t; }"
        : "=r"(a) : "l"(p));
    return a;
}

// pack (bf16-trunc(a), bf16-trunc(b)) -- exact hi parts
__device__ __forceinline__ uint32_t hi2(float a, float b) {
    return __byte_perm(__float_as_uint(a), __float_as_uint(b), 0x7632);
}
__device__ __forceinline__ float hitrunc(float a) {
    return __uint_as_float(__float_as_uint(a) & 0xFFFF0000u);
}
// pack rn-bf16 of the two residuals
__device__ __forceinline__ uint32_t lo2(float a, float b) {
    __nv_bfloat162 t = __floats2bfloat162_rn(a - hitrunc(a), b - hitrunc(b));
    return *(uint32_t*)&t;
}
__device__ __forceinline__ unsigned short hi1(float a) {
    return (unsigned short)(__float_as_uint(a) >> 16);
}
__device__ __forceinline__ unsigned short lo1(float a) {
    __nv_bfloat16 t = __float2bfloat16_rn(a - hitrunc(a));
    return *(unsigned short*)&t;
}

#define LDSM_X4(R0, R1, R2, R3, A)                                            \
    asm volatile("ldmatrix.sync.aligned.m8n8.x4.shared.b16 {%0,%1,%2,%3}, [%4];" \
                 : "=r"(R0), "=r"(R1), "=r"(R2), "=r"(R3) : "r"(A))

#define MMA_BF16(c, a, b)                                                     \
    asm volatile("mma.sync.aligned.m16n8k16.row.col.f32.bf16.bf16.f32 "       \
                 "{%0,%1,%2,%3}, {%4,%5,%6,%7}, {%8,%9}, {%0,%1,%2,%3};"      \
                 : "+f"((c)[0]), "+f"((c)[1]), "+f"((c)[2]), "+f"((c)[3])     \
                 : "r"((a)[0]), "r"((a)[1]), "r"((a)[2]), "r"((a)[3]),        \
                   "r"((b)[0]), "r"((b)[1]))

// smem geometry for K=32-chunk GEMMs: row = [32 hi][32 lo][8 pad] bf16
constexpr int SROW = 72;                   // 144 B row stride (16B multiple)
constexpr int TILE_HB = 128 * SROW * 2;    // 18432 B per operand tile
constexpr int GEMM_SMEM = 4 * TILE_HB;     // double buffer * (A,B)

// ---------------- Kernel 0: transpose + split x -> [b][w][c] planes ---------
// NOTE: row stride 65 floats (260 B) is NOT 16B-aligned -> phase-1 stores must
// be scalar (the R4/R5 fault was a float4 store here).

__global__ void __launch_bounds__(256)
transpose_x_kernel(const float* __restrict__ x) {
    __shared__ float s[64][65];
    const int b  = blockIdx.z;
    const int c0 = blockIdx.y * 64;
    const int w0 = blockIdx.x * 64;
    const int tid = threadIdx.x;

#pragma unroll
    for (int it = 0; it < 4; it++) {
        int c  = it * 16 + (tid >> 4);
        int w4 = (tid & 15) * 4;
        float4 v =
            *(const float4*)(x + ((size_t)b * NC + c0 + c) * NW + w0 + w4);
        s[c][w4 + 0] = v.x; s[c][w4 + 1] = v.y;
        s[c][w4 + 2] = v.z; s[c][w4 + 3] = v.w;
    }
    __syncthreads();

#pragma unroll
    for (int it = 0; it < 4; it++) {
        int w  = it * 16 + (tid >> 4);
        int c4 = (tid & 15) * 4;
        float f0 = s[c4 + 0][w], f1 = s[c4 + 1][w];
        float f2 = s[c4 + 2][w], f3 = s[c4 + 3][w];
        size_t o = ((size_t)b * NW + w0 + w) * NC + c0 + c4;
        *(uint2*)(g_xth + o) = make_uint2(hi2(f0, f1), hi2(f2, f3));
        *(uint2*)(g_xtl + o) = make_uint2(lo2(f0, f1), lo2(f2, f3));
    }
}

// ---------------- Kernel 1: QKV GEMM on tensor pipe -------------------------
// Y[m, w] = sum_c Wall[m, c] * x[c, w] + bias.  A = Wall (row-major fp32,
// converted in loader), B = x^T planes [w][c].  m-tile 0 = q(64)+k(64),
// m-tiles 1..4 = v.  q,k written transposed to g_qk* [b][pos][ch]; v natural.

__global__ void __launch_bounds__(256, 1)
qkv_mma_kernel(const float* __restrict__ x,
               const float* __restrict__ Wq, const float* __restrict__ bq,
               const float* __restrict__ Wk, const float* __restrict__ bk,
               const float* __restrict__ Wv, const float* __restrict__ bv) {
    extern __shared__ uint16_t smem[];
    const int b  = blockIdx.z;
    const int m0 = blockIdx.y * 128;
    const int w0 = blockIdx.x * 128;
    const int tid  = threadIdx.x;
    const int wid  = tid >> 5;
    const int lane = tid & 31;
    const int wm = wid >> 2, wn = wid & 3;

    const uint32_t sbase = smem_u32(smem);

    // loader mapping
    const int lrow = tid >> 1;
    const int lcol = (tid & 1) * 16;
    const int am_g = m0 + lrow;
    const float* srcA;
    if (am_g < NQ)            srcA = Wq + (size_t)am_g * NC;
    else if (am_g < 2 * NQ)   srcA = Wk + (size_t)(am_g - NQ) * NC;
    else                      srcA = Wv + (size_t)(am_g - 2 * NQ) * NC;
    srcA += lcol;
    const uint16_t* srcBh = g_xth + ((size_t)b * NW + w0 + lrow) * NC + lcol;
    const uint16_t* srcBl = g_xtl + ((size_t)b * NW + w0 + lrow) * NC + lcol;

    float acc[4][4][4];
#pragma unroll
    for (int mf = 0; mf < 4; mf++)
#pragma unroll
        for (int nf = 0; nf < 4; nf++)
#pragma unroll
            for (int e = 0; e < 4; e++) acc[mf][nf][e] = 0.f;

    float4 pa[4];
    uint4 pbh[2], pbl[2];
#pragma unroll
    for (int q = 0; q < 4; q++) pa[q] = *(const float4*)(srcA + 4 * q);
#pragma unroll
    for (int q = 0; q < 2; q++) {
        pbh[q] = *(const uint4*)(srcBh + 8 * q);
        pbl[q] = *(const uint4*)(srcBl + 8 * q);
    }

#pragma unroll 1
    for (int chunk = 0; chunk < NC / 32; chunk++) {
        const int p = chunk & 1;
        uint16_t* sA = smem + p * (2 * TILE_HB / 2);
        uint16_t* sB = sA + TILE_HB / 2;

        // A: convert fp32 -> hi/lo
#pragma unroll
        for (int q = 0; q < 4; q++) {
            const float* f = (const float*)&pa[q];
            *(uint2*)(sA + lrow * SROW + lcol + 4 * q) =
                make_uint2(hi2(f[0], f[1]), hi2(f[2], f[3]));
            *(uint2*)(sA + lrow * SROW + 32 + lcol + 4 * q) =
                make_uint2(lo2(f[0], f[1]), lo2(f[2], f[3]));
        }
        // B: direct bf16 copies
#pragma unroll
        for (int q = 0; q < 2; q++) {
            *(uint4*)(sB + lrow * SROW + lcol + 8 * q)      = pbh[q];
            *(uint4*)(sB + lrow * SROW + 32 + lcol + 8 * q) = pbl[q];
        }
        __syncthreads();

        if (chunk < NC / 32 - 1) {
            const int kk = (chunk + 1) * 32;
#pragma unroll
            for (int q = 0; q < 4; q++) pa[q] = *(const float4*)(srcA + kk + 4 * q);
#pragma unroll
            for (int q = 0; q < 2; q++) {
                pbh[q] = *(const uint4*)(srcBh + kk + 8 * q);
                pbl[q] = *(const uint4*)(srcBl + kk + 8 * q);
            }
        }

        const uint32_t aBase = sbase + p * 2 * TILE_HB;
        const uint32_t bBase = aBase + TILE_HB;
#pragma unroll
        for (int ks = 0; ks < 2; ks++) {
            const int kb = ks * 16;
            uint32_t Ah[4][4], Al[4][4], Bh[4][2], Bl[4][2];
            const int am = wm * 64 + (lane & 15);
            const int ak = kb + ((lane >> 4) << 3);
#pragma unroll
            for (int mf = 0; mf < 4; mf++) {
                uint32_t addr = aBase + ((am + mf * 16) * SROW + ak) * 2;
                LDSM_X4(Ah[mf][0], Ah[mf][1], Ah[mf][2], Ah[mf][3], addr);
                LDSM_X4(Al[mf][0], Al[mf][1], Al[mf][2], Al[mf][3], addr + 64);
            }
            const int bn = wn * 32 + ((lane >> 4) << 3) + (lane & 7);
            const int bk = kb + (((lane >> 3) & 1) << 3);
#pragma unroll
            for (int nfp = 0; nfp < 2; nfp++) {
                uint32_t addr = bBase + ((bn + nfp * 16) * SROW + bk) * 2;
                LDSM_X4(Bh[2 * nfp][0], Bh[2 * nfp][1],
                        Bh[2 * nfp + 1][0], Bh[2 * nfp + 1][1], addr);
                LDSM_X4(Bl[2 * nfp][0], Bl[2 * nfp][1],
                        Bl[2 * nfp + 1][0], Bl[2 * nfp + 1][1], addr + 64);
            }
#pragma unroll
            for (int mf = 0; mf < 4; mf++)
#pragma unroll
                for (int nf = 0; nf < 4; nf++) {
                    MMA_BF16(acc[mf][nf], Ah[mf], Bh[nf]);
                    MMA_BF16(acc[mf][nf], Ah[mf], Bl[nf]);
                    MMA_BF16(acc[mf][nf], Al[mf], Bh[nf]);
                }
        }
    }

    // epilogue
#pragma unroll
    for (int mf = 0; mf < 4; mf++) {
#pragma unroll
        for (int half = 0; half < 2; half++) {
            const int m = m0 + wm * 64 + mf * 16 + (lane >> 2) + 8 * half;
            if (m0 == 0 && m < 128) {
                // q/k channel -> transposed planes, col == m
                const float bias = (m < NQ) ? bq[m] : bk[m - NQ];
#pragma unroll
                for (int nf = 0; nf < 4; nf++) {
                    const int n = w0 + wn * 32 + nf * 8 + ((lane & 3) << 1);
                    float y0 = acc[mf][nf][2 * half + 0] + bias;
                    float y1 = acc[mf][nf][2 * half + 1] + bias;
                    size_t o0 = ((size_t)b * NW + n) * 128 + m;
                    size_t o1 = o0 + 128;
                    g_qkh[o0] = hi1(y0); g_qkl[o0] = lo1(y0);
                    g_qkh[o1] = hi1(y1); g_qkl[o1] = lo1(y1);
                }
            } else if (m0 > 0) {
                const int c = m - 128;
                const float bias = bv[c];
#pragma unroll
                for (int nf = 0; nf < 4; nf++) {
                    const int n = w0 + wn * 32 + nf * 8 + ((lane & 3) << 1);
                    float y0 = acc[mf][nf][2 * half + 0] + bias;
                    float y1 = acc[mf][nf][2 * half + 1] + bias;
                    size_t o = ((size_t)b * NC + c) * NW + n;
                    *(uint32_t*)(g_vh + o) = hi2(y0, y1);
                    *(uint32_t*)(g_vl + o) = lo2(y0, y1);
                }
            }
        }
    }
}

// ---------------- Kernel 2: energy on tensor pipe ---------------------------
// S[i,j] = sum_q q[i,q] k[j,q].  A = qk planes cols 0:64 rows i; B = cols
// 64:128 rows j.  K = 64, single load, 4 k-steps.  smem row = [64hi][64lo][8].

constexpr int SROWE   = 136;                 // 272 B (16B multiple)
constexpr int TILE_EB = 128 * SROWE * 2;     // 34816 B
constexpr int EN_SMEM = 2 * TILE_EB;

__global__ void __launch_bounds__(256, 1)
energy_mma_kernel() {
    extern __shared__ uint16_t smem[];
    const int b  = blockIdx.z;
    const int i0 = blockIdx.y * 128;
    const int j0 = blockIdx.x * 128;
    const int tid  = threadIdx.x;
    const int wid  = tid >> 5;
    const int lane = tid & 31;
    const int wm = wid >> 2, wn = wid & 3;

    const uint32_t sbase = smem_u32(smem);
    uint16_t* sA = smem;
    uint16_t* sB = smem + TILE_EB / 2;

    const int lrow = tid >> 1;
    const int half = (tid & 1) * 32;
    {
        const uint16_t* qh = g_qkh + ((size_t)b * NW + i0 + lrow) * 128 + half;
        const uint16_t* ql = g_qkl + ((size_t)b * NW + i0 + lrow) * 128 + half;
        const uint16_t* kh = g_qkh + ((size_t)b * NW + j0 + lrow) * 128 + 64 + half;
        const uint16_t* kl = g_qkl + ((size_t)b * NW + j0 + lrow) * 128 + 64 + half;
#pragma unroll
        for (int q = 0; q < 4; q++) {
            *(uint4*)(sA + lrow * SROWE + half + 8 * q)      = *(const uint4*)(qh + 8 * q);
            *(uint4*)(sA + lrow * SROWE + 64 + half + 8 * q) = *(const uint4*)(ql + 8 * q);
            *(uint4*)(sB + lrow * SROWE + half + 8 * q)      = *(const uint4*)(kh + 8 * q);
            *(uint4*)(sB + lrow * SROWE + 64 + half + 8 * q) = *(const uint4*)(kl + 8 * q);
        }
    }
    __syncthreads();

    float acc[4][4][4];
#pragma unroll
    for (int mf = 0; mf < 4; mf++)
#pragma unroll
        for (int nf = 0; nf < 4; nf++)
#pragma unroll
            for (int e = 0; e < 4; e++) acc[mf][nf][e] = 0.f;

    const uint32_t aBase = sbase;
    const uint32_t bBase = sbase + TILE_EB;
#pragma unroll
    for (int ks = 0; ks < 4; ks++) {
        const int kb = ks * 16;
        uint32_t Ah[4][4], Al[4][4], Bh[4][2], Bl[4][2];
        const int am = wm * 64 + (lane & 15);
        const int ak = kb + ((lane >> 4) << 3);
#pragma unroll
        for (int mf = 0; mf < 4; mf++) {
            uint32_t addr = aBase + ((am + mf * 16) * SROWE + ak) * 2;
            LDSM_X4(Ah[mf][0], Ah[mf][1], Ah[mf][2], Ah[mf][3], addr);
            LDSM_X4(Al[mf][0], Al[mf][1], Al[mf][2], Al[mf][3], addr + 128);
        }
        const int bn = wn * 32 + ((lane >> 4) << 3) + (lane & 7);
        const int bk = kb + (((lane >> 3) & 1) << 3);
#pragma unroll
        for (int nfp = 0; nfp < 2; nfp++) {
            uint32_t addr = bBase + ((bn + nfp * 16) * SROWE + bk) * 2;
            LDSM_X4(Bh[2 * nfp][0], Bh[2 * nfp][1],
                    Bh[2 * nfp + 1][0], Bh[2 * nfp + 1][1], addr);
            LDSM_X4(Bl[2 * nfp][0], Bl[2 * nfp][1],
                    Bl[2 * nfp + 1][0], Bl[2 * nfp + 1][1], addr + 128);
        }
#pragma unroll
        for (int mf = 0; mf < 4; mf++)
#pragma unroll
            for (int nf = 0; nf < 4; nf++) {
                MMA_BF16(acc[mf][nf], Ah[mf], Bh[nf]);
                MMA_BF16(acc[mf][nf], Ah[mf], Bl[nf]);
                MMA_BF16(acc[mf][nf], Al[mf], Bh[nf]);
            }
    }

#pragma unroll
    for (int mf = 0; mf < 4; mf++) {
        const int m = i0 + wm * 64 + mf * 16 + (lane >> 2);
#pragma unroll
        for (int nf = 0; nf < 4; nf++) {
            const int n = j0 + wn * 32 + nf * 8 + ((lane & 3) << 1);
            size_t o0 = ((size_t)b * NW + m) * NW + n;
            *(float2*)(g_att + o0) = make_float2(acc[mf][nf][0], acc[mf][nf][1]);
            size_t o1 = o0 + (size_t)8 * NW;
            *(float2*)(g_att + o1) = make_float2(acc[mf][nf][2], acc[mf][nf][3]);
        }
    }
}

// ---------------- Kernel 3: row softmax, fp32 in, bf16 hi/lo planes out -----

__global__ void __launch_bounds__(256)
softmax_kernel() {
    __shared__ float red[8];
    const size_t row = blockIdx.x;
    const float* p = g_att + row * NW;
    const int tid = threadIdx.x;

    float4 v0 = *(const float4*)(p + tid * 8);
    float4 v1 = *(const float4*)(p + tid * 8 + 4);
    float e[8] = {v0.x, v0.y, v0.z, v0.w, v1.x, v1.y, v1.z, v1.w};

    float m = e[0];
#pragma unroll
    for (int i = 1; i < 8; i++) m = fmaxf(m, e[i]);
#pragma unroll
    for (int o = 16; o; o >>= 1) m = fmaxf(m, __shfl_xor_sync(0xffffffffu, m, o));
    if ((tid & 31) == 0) red[tid >> 5] = m;
    __syncthreads();
    m = red[0];
#pragma unroll
    for (int i = 1; i < 8; i++) m = fmaxf(m, red[i]);

    float s = 0.f;
#pragma unroll
    for (int i = 0; i < 8; i++) { e[i] = __expf(e[i] - m); s += e[i]; }
#pragma unroll
    for (int o = 16; o; o >>= 1) s += __shfl_xor_sync(0xffffffffu, s, o);
    __syncthreads();
    if ((tid & 31) == 0) red[tid >> 5] = s;
    __syncthreads();
    s = 0.f;
#pragma unroll
    for (int i = 0; i < 8; i++) s += red[i];

    float inv = 1.0f / s;
#pragma unroll
    for (int i = 0; i < 8; i++) e[i] *= inv;

    uint4 hv = make_uint4(hi2(e[0], e[1]), hi2(e[2], e[3]),
                          hi2(e[4], e[5]), hi2(e[6], e[7]));
    uint4 lv = make_uint4(lo2(e[0], e[1]), lo2(e[2], e[3]),
                          lo2(e[4], e[5]), lo2(e[6], e[7]));
    *(uint4*)(g_ph + row * NW + tid * 8) = hv;
    *(uint4*)(g_pl + row * NW + tid * 8) = lv;
}

// ---------------- Kernel 4: out GEMM, pure-bf16 loads -----------------------
// out[c, i] = gamma * sum_j v[c,j] P[i,j] + x[c,i]

__global__ void __launch_bounds__(256, 1)
out_mma_kernel(const float* __restrict__ x, const float* __restrict__ gamma,
               float* __restrict__ out) {
    extern __shared__ uint16_t smem[];
    const int b  = blockIdx.z;
    const int c0 = blockIdx.x * 128;
    const int i0 = blockIdx.y * 128;
    const int tid  = threadIdx.x;
    const int wid  = tid >> 5;
    const int lane = tid & 31;
    const int wm = wid >> 2, wn = wid & 3;

    const uint32_t sbase = smem_u32(smem);

    const int lrow = tid >> 1;
    const int lcol = (tid & 1) * 16;
    const uint16_t* gAh = g_vh + ((size_t)b * NC + c0 + lrow) * NW + lcol;
    const uint16_t* gAl = g_vl + ((size_t)b * NC + c0 + lrow) * NW + lcol;
    const uint16_t* gBh = g_ph + ((size_t)b * NW + i0 + lrow) * NW + lcol;
    const uint16_t* gBl = g_pl + ((size_t)b * NW + i0 + lrow) * NW + lcol;

    float acc[4][4][4];
#pragma unroll
    for (int mf = 0; mf < 4; mf++)
#pragma unroll
        for (int nf = 0; nf < 4; nf++)
#pragma unroll
            for (int e = 0; e < 4; e++) acc[mf][nf][e] = 0.f;

    uint4 pah[2], pal[2], pbh[2], pbl[2];
#pragma unroll
    for (int q = 0; q < 2; q++) {
        pah[q] = *(const uint4*)(gAh + 8 * q);
        pal[q] = *(const uint4*)(gAl + 8 * q);
        pbh[q] = *(const uint4*)(gBh + 8 * q);
        pbl[q] = *(const uint4*)(gBl + 8 * q);
    }

#pragma unroll 1
    for (int chunk = 0; chunk < NW / 32; chunk++) {
        const int p = chunk & 1;
        uint16_t* sA = smem + p * (2 * TILE_HB / 2);
        uint16_t* sB = sA + TILE_HB / 2;

#pragma unroll
        for (int q = 0; q < 2; q++) {
            *(uint4*)(sA + lrow * SROW + lcol + 8 * q)      = pah[q];
            *(uint4*)(sA + lrow * SROW + 32 + lcol + 8 * q) = pal[q];
            *(uint4*)(sB + lrow * SROW + lcol + 8 * q)      = pbh[q];
            *(uint4*)(sB + lrow * SROW + 32 + lcol + 8 * q) = pbl[q];
        }
        __syncthreads();

        if (chunk < NW / 32 - 1) {
            const int kk = (chunk + 1) * 32;
#pragma unroll
            for (int q = 0; q < 2; q++) {
                pah[q] = *(const uint4*)(gAh + kk + 8 * q);
                pal[q] = *(const uint4*)(gAl + kk + 8 * q);
                pbh[q] = *(const uint4*)(gBh + kk + 8 * q);
                pbl[q] = *(const uint4*)(gBl + kk + 8 * q);
            }
        }

        const uint32_t aBase = sbase + p * 2 * TILE_HB;
        const uint32_t bBase = aBase + TILE_HB;
#pragma unroll
        for (int ks = 0; ks < 2; ks++) {
            const int kb = ks * 16;
            uint32_t Ah[4][4], Al[4][4], Bh[4][2], Bl[4][2];
            const int am = wm * 64 + (lane & 15);
            const int ak = kb + ((lane >> 4) << 3);
#pragma unroll
            for (int mf = 0; mf < 4; mf++) {
                uint32_t addr = aBase + ((am + mf * 16) * SROW + ak) * 2;
                LDSM_X4(Ah[mf][0], Ah[mf][1], Ah[mf][2], Ah[mf][3], addr);
                LDSM_X4(Al[mf][0], Al[mf][1], Al[mf][2], Al[mf][3], addr + 64);
            }
            const int bn = wn * 32 + ((lane >> 4) << 3) + (lane & 7);
            const int bk = kb + (((lane >> 3) & 1) << 3);
#pragma unroll
            for (int nfp = 0; nfp < 2; nfp++) {
                uint32_t addr = bBase + ((bn + nfp * 16) * SROW + bk) * 2;
                LDSM_X4(Bh[2 * nfp][0], Bh[2 * nfp][1],
                        Bh[2 * nfp + 1][0], Bh[2 * nfp + 1][1], addr);
                LDSM_X4(Bl[2 * nfp][0], Bl[2 * nfp][1],
                        Bl[2 * nfp + 1][0], Bl[2 * nfp + 1][1], addr + 64);
            }
#pragma unroll
            for (int mf = 0; mf < 4; mf++)
#pragma unroll
                for (int nf = 0; nf < 4; nf++) {
                    MMA_BF16(acc[mf][nf], Ah[mf], Bh[nf]);
                    MMA_BF16(acc[mf][nf], Ah[mf], Bl[nf]);
                    MMA_BF16(acc[mf][nf], Al[mf], Bh[nf]);
                }
        }
    }

    const float gam = gamma[0];
#pragma unroll
    for (int mf = 0; mf < 4; mf++) {
        const int m = c0 + wm * 64 + mf * 16 + (lane >> 2);
#pragma unroll
        for (int nf = 0; nf < 4; nf++) {
            const int n = i0 + wn * 32 + nf * 8 + ((lane & 3) << 1);
            size_t o0 = ((size_t)b * NC + m) * NW + n;
            float2 xv0 = *(const float2*)(x + o0);
            *(float2*)(out + o0) = make_float2(fmaf(gam, acc[mf][nf][0], xv0.x),
                                               fmaf(gam, acc[mf][nf][1], xv0.y));
            size_t o1 = o0 + (size_t)8 * NW;
            float2 xv1 = *(const float2*)(x + o1);
            *(float2*)(out + o1) = make_float2(fmaf(gam, acc[mf][nf][2], xv1.x),
                                               fmaf(gam, acc[mf][nf][3], xv1.y));
        }
    }
}

// ---------------- launch ----------------------------------------------------

extern "C" void kernel_launch(void* const* d_in, const int* in_sizes, int n_in,
                              void* d_out, int out_size) {
    const float* x     = (const float*)d_in[0];
    const float* Wq    = (const float*)d_in[1];
    const float* bq    = (const float*)d_in[2];
    const float* Wk    = (const float*)d_in[3];
    const float* bk    = (const float*)d_in[4];
    const float* Wv    = (const float*)d_in[5];
    const float* bv    = (const float*)d_in[6];
    const float* gamma = (const float*)d_in[7];
    float* out = (float*)d_out;

    cudaFuncSetAttribute(qkv_mma_kernel,
                         cudaFuncAttributeMaxDynamicSharedMemorySize, GEMM_SMEM);
    cudaFuncSetAttribute(energy_mma_kernel,
                         cudaFuncAttributeMaxDynamicSharedMemorySize, EN_SMEM);
    cudaFuncSetAttribute(out_mma_kernel,
                         cudaFuncAttributeMaxDynamicSharedMemorySize, GEMM_SMEM);

    transpose_x_kernel<<<dim3(NW / 64, NC / 64, NB), 256>>>(x);
    qkv_mma_kernel<<<dim3(NW / 128, 5, NB), 256, GEMM_SMEM>>>(
        x, Wq, bq, Wk, bk, Wv, bv);
    energy_mma_kernel<<<dim3(NW / 128, NW / 128, NB), 256, EN_SMEM>>>();
    softmax_kernel<<<NB * NW, 256>>>();
    out_mma_kernel<<<dim3(NC / 128, NW / 128, NB), 256, GEMM_SMEM>>>(x, gamma, out);
}